// round 4
// baseline (speedup 1.0000x reference)
#include <cuda_runtime.h>
#include <math.h>

#define NN   10000
#define NE   320000
#define BB   8
#define TTI  12
#define CIN  2
#define HH   64
#define NBT  (NN*BB*TTI)       /* 960000 positions */
#define TOT  (NBT*HH)          /* 61,440,000 floats */
#define FDIM (BB*TTI*HH)       /* 6144 */
#define F4   (FDIM/4)          /* 1536 */

typedef unsigned long long ull;

// ---------------- f32x2 packed-FMA helpers (sm_100+) ----------------
__device__ __forceinline__ ull pack2(float a, float b) {
    ull r;
    asm("mov.b64 %0, {%1, %2};" : "=l"(r) : "f"(a), "f"(b));
    return r;
}
__device__ __forceinline__ void unpack2(float& lo, float& hi, ull v) {
    asm("mov.b64 {%0, %1}, %2;" : "=f"(lo), "=f"(hi) : "l"(v));
}
__device__ __forceinline__ void fma2(ull& d, ull a, ull b) {
    asm("fma.rn.f32x2 %0, %1, %2, %0;" : "+l"(d) : "l"(a), "l"(b));
}

// ---------------- scratch (device globals; no allocs allowed) ----------------
__device__ __align__(16) float g_T0[TOT];
__device__ __align__(16) float g_Y1[TOT];
__device__ __align__(16) float g_Y2[TOT];
__device__ __align__(16) float g_S [TOT];
__device__ float g_degw[NN];
__device__ int   g_cnt[NN];
__device__ float g_dis[NN];
__device__ int   g_rowptr[NN+1];
__device__ int   g_cursor[NN];
__device__ int   g_colidx[NE];
__device__ float g_ew[NE];

// ---------------- CSR build ----------------
__global__ void init_kernel() {
    int i = blockIdx.x*256 + threadIdx.x;
    if (i < NN) { g_degw[i] = 0.f; g_cnt[i] = 0; }
}

__global__ void hist_kernel(const int* __restrict__ row, const float* __restrict__ ew) {
    int e = blockIdx.x*256 + threadIdx.x;
    if (e < NE) {
        int r = row[e];
        atomicAdd(&g_degw[r], ew[e]);
        atomicAdd(&g_cnt[r], 1);
    }
}

// single-block exclusive scan of g_cnt -> g_rowptr, g_cursor; also g_dis
__global__ void scan_kernel() {
    __shared__ int s[1024];
    int tid = threadIdx.x;
    int lo = tid * 10;
    int sum = 0;
    for (int r = lo; r < lo+10 && r < NN; r++) {
        sum += g_cnt[r];
        float d = g_degw[r];
        g_dis[r] = d > 0.f ? rsqrtf(d) : 0.f;
    }
    s[tid] = sum;
    __syncthreads();
    for (int off = 1; off < 1024; off <<= 1) {
        int v = (tid >= off) ? s[tid-off] : 0;
        __syncthreads();
        s[tid] += v;
        __syncthreads();
    }
    int run = s[tid] - sum;   // exclusive prefix
    for (int r = lo; r < lo+10 && r < NN; r++) {
        g_rowptr[r] = run;
        g_cursor[r] = run;
        run += g_cnt[r];
    }
    if (tid == 1023) g_rowptr[NN] = s[1023];
}

__global__ void scatter_kernel(const int* __restrict__ row, const int* __restrict__ col,
                               const float* __restrict__ ew) {
    int e = blockIdx.x*256 + threadIdx.x;
    if (e < NE) {
        int r = row[e], c = col[e];
        int p = atomicAdd(&g_cursor[r], 1);
        g_colidx[p] = c;
        g_ew[p] = -g_dis[r] * ew[e] * g_dis[c];   // L_hat weight (sym norm, lambda_max=2)
    }
}

// ---------------- temporal conv 1:  X[B,T,N,C] -> g_T0[N,B,T,H] ----------------
__global__ __launch_bounds__(256) void tconv1_kernel(const float* __restrict__ X,
        const float* __restrict__ w1, const float* __restrict__ b1,
        const float* __restrict__ w2, const float* __restrict__ b2,
        const float* __restrict__ w3, const float* __restrict__ b3) {
    __shared__ float sw[3][HH*CIN*3];
    __shared__ float sb[3][HH];
    int tid = threadIdx.y*64 + threadIdx.x;
    for (int i = tid; i < HH*CIN*3; i += 256) { sw[0][i]=w1[i]; sw[1][i]=w2[i]; sw[2][i]=w3[i]; }
    if (tid < HH) { sb[0][tid]=b1[tid]; sb[1][tid]=b2[tid]; sb[2][tid]=b3[tid]; }
    __syncthreads();

    int pos = blockIdx.x*4 + threadIdx.y;        // pos = (n*B + b)*T + t
    int h = threadIdx.x;
    int t  = pos % TTI;
    int nb = pos / TTI;
    int b  = nb % BB;
    int n  = nb / BB;

    float xv[3][CIN];
#pragma unroll
    for (int k = 0; k < 3; k++) {
        int t2 = t + k - 1;
        if (t2 >= 0 && t2 < TTI) {
#pragma unroll
            for (int c = 0; c < CIN; c++)
                xv[k][c] = X[((b*TTI + t2)*NN + n)*CIN + c];
        } else {
            xv[k][0] = 0.f; xv[k][1] = 0.f;
        }
    }
    float p = sb[0][h], q = sb[1][h], r = sb[2][h];
#pragma unroll
    for (int c = 0; c < CIN; c++)
#pragma unroll
        for (int k = 0; k < 3; k++) {
            float v = xv[k][c];
            p += v * sw[0][h*6 + c*3 + k];
            q += v * sw[1][h*6 + c*3 + k];
            r += v * sw[2][h*6 + c*3 + k];
        }
    float sg = 1.f / (1.f + expf(-q));
    g_T0[pos*HH + h] = fmaxf(p*sg + r, 0.f);
}

// ---------------- graph prop: y[n,:] = sum_e w[e] * x[col[e],:] ----------------
// grid (NN, 6): blockIdx.x fastest -> all nodes of one 1024-float feature chunk
// run together => 41MB L2-resident working set per chunk.
__global__ __launch_bounds__(256) void prop_kernel(int mode) {
    const float4* __restrict__ x = (const float4*)(mode ? g_Y1 : g_T0);
    float4* __restrict__ y       = (float4*)(mode ? g_Y2 : g_Y1);
    int n = blockIdx.x;
    int f = blockIdx.y*256 + threadIdx.x;     // float4 index in [0,1536)
    int beg = g_rowptr[n], end = g_rowptr[n+1];
    float4 acc = make_float4(0.f, 0.f, 0.f, 0.f);
    int e = beg;
    for (; e + 4 <= end; e += 4) {
        int   c0 = g_colidx[e],   c1 = g_colidx[e+1], c2 = g_colidx[e+2], c3 = g_colidx[e+3];
        float w0 = g_ew[e],       w1 = g_ew[e+1],     w2 = g_ew[e+2],     w3 = g_ew[e+3];
        float4 v0 = x[c0*F4 + f], v1 = x[c1*F4 + f],  v2 = x[c2*F4 + f],  v3 = x[c3*F4 + f];
        acc.x += w0*v0.x + w1*v1.x + w2*v2.x + w3*v3.x;
        acc.y += w0*v0.y + w1*v1.y + w2*v2.y + w3*v3.y;
        acc.z += w0*v0.z + w1*v1.z + w2*v2.z + w3*v3.z;
        acc.w += w0*v0.w + w1*v1.w + w2*v2.w + w3*v3.w;
    }
    for (; e < end; e++) {
        int c = g_colidx[e]; float w = g_ew[e];
        float4 v = x[c*F4 + f];
        acc.x += w*v.x; acc.y += w*v.y; acc.z += w*v.z; acc.w += w*v.w;
    }
    y[n*F4 + f] = acc;
}

// ---------------- cheb combine: S = relu(T0@W0 + Y1@W1 + (2*Y2-T0)@W2 + b) ----
// block = 64 positions. f32x2 packed FMA: thread owns 8 positions x {og, og+32}.
// Ws: [m][i*65+h] (broadcast scalar reads). xs transposed: [m][i*66+p] so
// position-pairs are contiguous 8B-aligned for LDS.64.
#define CMB_WS_F (3*64*65)          /* 12480 */
#define CMB_XS_F (3*64*66)          /* 12672 */
#define CMB_SMEM_BYTES ((CMB_WS_F + CMB_XS_F + 64)*4)
__global__ __launch_bounds__(256) void combine_kernel(const float* __restrict__ Wc,
                                                      const float* __restrict__ bias) {
    extern __shared__ float sm[];
    float* Ws = sm;                         // [m*4160 + i*65 + h]
    float* xs = sm + CMB_WS_F;              // [m*4224 + i*66 + p]
    float* bs = xs + CMB_XS_F;
    int tid = threadIdx.x;
    for (int idx = tid; idx < 3*64*64; idx += 256) {
        int m = idx >> 12; int r = idx & 4095; int i = r >> 6; int h = r & 63;
        Ws[m*4160 + i*65 + h] = Wc[idx];
    }
    if (tid < 64) bs[tid] = bias[tid];
    int base = blockIdx.x * 4096;           // 64 positions * 64
    for (int idx = tid; idx < 4096; idx += 256) {
        int p = idx >> 6, i = idx & 63;
        float a = g_T0[base+idx], u = g_Y1[base+idx], v = g_Y2[base+idx];
        xs[i*66 + p]        = a;
        xs[4224 + i*66 + p] = u;
        xs[8448 + i*66 + p] = 2.f*v - a;
    }
    __syncthreads();

    int og = tid & 31, pg = tid >> 5;
    int p0 = pg * 8;                        // 8 positions per thread (4 pairs)
    ull a0[4], a1[4];
    {
        ull b0 = pack2(bs[og], bs[og]);
        ull b1 = pack2(bs[og+32], bs[og+32]);
#pragma unroll
        for (int pr = 0; pr < 4; pr++) { a0[pr] = b0; a1[pr] = b1; }
    }
#pragma unroll 2
    for (int i = 0; i < 64; i++) {
        float w00 = Ws[i*65+og],        w01 = Ws[i*65+og+32];
        float w10 = Ws[4160+i*65+og],   w11 = Ws[4160+i*65+og+32];
        float w20 = Ws[8320+i*65+og],   w21 = Ws[8320+i*65+og+32];
        ull W00 = pack2(w00,w00), W01 = pack2(w01,w01);
        ull W10 = pack2(w10,w10), W11 = pack2(w11,w11);
        ull W20 = pack2(w20,w20), W21 = pack2(w21,w21);
        int xo = i*66 + p0;
#pragma unroll
        for (int pr = 0; pr < 4; pr++) {
            ull x0 = *(const ull*)(xs + xo + 2*pr);
            ull x1 = *(const ull*)(xs + 4224 + xo + 2*pr);
            ull x2 = *(const ull*)(xs + 8448 + xo + 2*pr);
            fma2(a0[pr], x0, W00); fma2(a1[pr], x0, W01);
            fma2(a0[pr], x1, W10); fma2(a1[pr], x1, W11);
            fma2(a0[pr], x2, W20); fma2(a1[pr], x2, W21);
        }
    }
#pragma unroll
    for (int pr = 0; pr < 4; pr++) {
        float v0, v1;
        unpack2(v0, v1, a0[pr]);
        g_S[base + (p0+2*pr)*64   + og] = fmaxf(v0, 0.f);
        g_S[base + (p0+2*pr+1)*64 + og] = fmaxf(v1, 0.f);
        unpack2(v0, v1, a1[pr]);
        g_S[base + (p0+2*pr)*64   + og + 32] = fmaxf(v0, 0.f);
        g_S[base + (p0+2*pr+1)*64 + og + 32] = fmaxf(v1, 0.f);
    }
}

// ---------------- temporal conv 2: g_S[N,B,T,H] -> out[B,T,N,H] ---------------
// block = 16 (n,b) pairs (192 positions). Weights packed (og, og+32) float2
// for f32x2; padded x tiles in smem.
#define T2_WP_F2 (3*192*32)         /* 18432 float2 = 144KB */
#define T2_XS_F  (16*14*64)         /* 14336 floats = 56KB */
#define T2_SMEM_BYTES (T2_WP_F2*8 + T2_XS_F*4 + 192*4)
__global__ __launch_bounds__(256) void tconv2_kernel(
        const float* __restrict__ w1, const float* __restrict__ b1,
        const float* __restrict__ w2, const float* __restrict__ b2,
        const float* __restrict__ w3, const float* __restrict__ b3,
        float* __restrict__ out) {
    extern __shared__ float sm[];
    float2* Wp = (float2*)sm;               // [m][j*32+og] = (w[og][j], w[og+32][j])
    float*  xs = sm + 2*T2_WP_F2;           // [pair][tt*64 + c], tt=0..13 (zero-padded ends)
    float*  bs = xs + T2_XS_F;
    int tid = threadIdx.x;
    for (int idx = tid; idx < 3*192*32; idx += 256) {
        int m = idx / 6144; int r = idx - m*6144; int j = r >> 5; int og = r & 31;
        const float* w = (m == 0) ? w1 : ((m == 1) ? w2 : w3);
        Wp[idx] = make_float2(w[og*192 + j], w[(og+32)*192 + j]);
    }
    if (tid < 64) { bs[tid]=b1[tid]; bs[64+tid]=b2[tid]; bs[128+tid]=b3[tid]; }
    int nb0 = blockIdx.x * 16;
    for (int idx = tid; idx < 16*TTI*64; idx += 256) {
        int pair = idx / 768; int r = idx - pair*768; int t = r >> 6; int c = r & 63;
        xs[pair*896 + (t+1)*64 + c] = g_S[(nb0+pair)*768 + t*64 + c];
    }
    for (int idx = tid; idx < 16*128; idx += 256) {
        int pair = idx >> 7; int r = idx & 127;
        int t = (r >> 6) ? 13 : 0; int c = r & 63;
        xs[pair*896 + t*64 + c] = 0.f;
    }
    __syncthreads();

    int og = tid & 31, pg = tid >> 5;
    ull bp = pack2(bs[og], bs[og+32]);
    ull bq = pack2(bs[64+og], bs[64+og+32]);
    ull br = pack2(bs[128+og], bs[128+og+32]);
    for (int chunk = 0; chunk < 6; chunk++) {
        ull aP[4], aQ[4], aR[4];
        int xbase[4], pidx[4];
#pragma unroll
        for (int pp = 0; pp < 4; pp++) {
            aP[pp]=bp; aQ[pp]=bq; aR[pp]=br;
            int p = chunk*32 + pg*4 + pp;          // 0..191
            int pair = p / 12, t = p - pair*12;
            xbase[pp] = pair*896 + t*64;           // tap k reads +k*64 (tt = t+k)
            pidx[pp] = p;
        }
        for (int k = 0; k < 3; k++) {
#pragma unroll 4
            for (int c = 0; c < 64; c++) {
                int j = c*3 + k;
                ull wp = *(const ull*)&Wp[j*32 + og];
                ull wq = *(const ull*)&Wp[6144 + j*32 + og];
                ull wr = *(const ull*)&Wp[12288 + j*32 + og];
#pragma unroll
                for (int pp = 0; pp < 4; pp++) {
                    float xv = xs[xbase[pp] + k*64 + c];
                    ull xx = pack2(xv, xv);
                    fma2(aP[pp], xx, wp);
                    fma2(aQ[pp], xx, wq);
                    fma2(aR[pp], xx, wr);
                }
            }
        }
#pragma unroll
        for (int pp = 0; pp < 4; pp++) {
            int p = pidx[pp]; int pair = p/12, t = p - pair*12;
            int nb = nb0 + pair; int n = nb >> 3; int b = nb & 7;
            int obase = ((b*TTI + t)*NN + n)*64;
            float P0,P1,Q0,Q1,R0,R1;
            unpack2(P0, P1, aP[pp]);
            unpack2(Q0, Q1, aQ[pp]);
            unpack2(R0, R1, aR[pp]);
            float sg0 = 1.f/(1.f + expf(-Q0));
            float sg1 = 1.f/(1.f + expf(-Q1));
            out[obase + og]      = fmaxf(P0*sg0 + R0, 0.f);
            out[obase + og + 32] = fmaxf(P1*sg1 + R1, 0.f);
        }
    }
}

// ---------------- launch ----------------
extern "C" void kernel_launch(void* const* d_in, const int* in_sizes, int n_in,
                              void* d_out, int out_size) {
    const float* X    = (const float*)d_in[0];
    const int*   ei   = (const int*)  d_in[1];
    const float* ew   = (const float*)d_in[2];
    const float* t1w1 = (const float*)d_in[3];  const float* t1b1 = (const float*)d_in[4];
    const float* t1w2 = (const float*)d_in[5];  const float* t1b2 = (const float*)d_in[6];
    const float* t1w3 = (const float*)d_in[7];  const float* t1b3 = (const float*)d_in[8];
    const float* cW   = (const float*)d_in[9];  const float* cb   = (const float*)d_in[10];
    const float* t2w1 = (const float*)d_in[11]; const float* t2b1 = (const float*)d_in[12];
    const float* t2w2 = (const float*)d_in[13]; const float* t2b2 = (const float*)d_in[14];
    const float* t2w3 = (const float*)d_in[15]; const float* t2b3 = (const float*)d_in[16];
    float* out = (float*)d_out;
    const int* row = ei;
    const int* col = ei + NE;

    cudaFuncSetAttribute(combine_kernel, cudaFuncAttributeMaxDynamicSharedMemorySize,
                         CMB_SMEM_BYTES);
    cudaFuncSetAttribute(tconv2_kernel, cudaFuncAttributeMaxDynamicSharedMemorySize,
                         T2_SMEM_BYTES);

    init_kernel   <<<(NN+255)/256, 256>>>();
    hist_kernel   <<<(NE+255)/256, 256>>>(row, ew);
    scan_kernel   <<<1, 1024>>>();
    scatter_kernel<<<(NE+255)/256, 256>>>(row, col, ew);

    tconv1_kernel <<<NBT/4, dim3(64,4)>>>(X, t1w1,t1b1, t1w2,t1b2, t1w3,t1b3);

    prop_kernel   <<<dim3(NN, 6), 256>>>(0);   // Y1 = L * T0   (ncu -s 5 lands here)
    prop_kernel   <<<dim3(NN, 6), 256>>>(1);   // Y2 = L * Y1

    combine_kernel<<<NBT/64, 256, CMB_SMEM_BYTES>>>(cW, cb);

    tconv2_kernel <<<NN*BB/16, 256, T2_SMEM_BYTES>>>(
        t2w1,t2b1, t2w2,t2b2, t2w3,t2b3, out);
}

// round 5
// speedup vs baseline: 1.0846x; 1.0846x over previous
#include <cuda_runtime.h>
#include <math.h>

#define NN   10000
#define NE   320000
#define BB   8
#define TTI  12
#define CIN  2
#define HH   64
#define NBT  (NN*BB*TTI)       /* 960000 positions */
#define TOT  (NBT*HH)          /* 61,440,000 floats */
#define F4   (BB*TTI*HH/4)     /* 1536 */

typedef unsigned long long ull;

// ---------------- f32x2 packed-FMA helpers (sm_100+) ----------------
__device__ __forceinline__ ull pack2(float a, float b) {
    ull r;
    asm("mov.b64 %0, {%1, %2};" : "=l"(r) : "f"(a), "f"(b));
    return r;
}
__device__ __forceinline__ void unpack2(float& lo, float& hi, ull v) {
    asm("mov.b64 {%0, %1}, %2;" : "=f"(lo), "=f"(hi) : "l"(v));
}
__device__ __forceinline__ void fma2(ull& d, ull a, ull b) {
    asm("fma.rn.f32x2 %0, %1, %2, %0;" : "+l"(d) : "l"(a), "l"(b));
}

// ---------------- scratch (device globals; zero-init at load) ----------------
__device__ __align__(16) float g_T0[TOT];
__device__ __align__(16) float g_Y1[TOT];
__device__ __align__(16) float g_Y2[TOT];
__device__ __align__(16) float g_S [TOT];
__device__ float g_degw[NN];    /* zeroed by cleanup_kernel at end of each call */
__device__ int   g_cnt[NN];     /* ditto */
__device__ float g_dis[NN];
__device__ int   g_rowptr[NN+1];
__device__ int   g_cursor[NN];
__device__ int   g_colidx[NE];
__device__ float g_ew[NE];

// ---------------- prep: tconv1 (blocks < T1_BLOCKS) + degree hist ------------
#define T1_BLOCKS  (NBT/4)      /* 240000 */
#define HIST_BLOCKS (NE/256)    /* 1250 */
__global__ __launch_bounds__(256) void prep_kernel(const float* __restrict__ X,
        const float* __restrict__ w1, const float* __restrict__ b1,
        const float* __restrict__ w2, const float* __restrict__ b2,
        const float* __restrict__ w3, const float* __restrict__ b3,
        const int* __restrict__ row, const float* __restrict__ ew) {
    if (blockIdx.x >= T1_BLOCKS) {
        int e = (int)(blockIdx.x - T1_BLOCKS)*256 + threadIdx.x;
        if (e < NE) {
            int r = row[e];
            atomicAdd(&g_degw[r], ew[e]);
            atomicAdd(&g_cnt[r], 1);
        }
        return;
    }
    __shared__ float sw[3][HH*CIN*3];
    __shared__ float sb[3][HH];
    int tid = threadIdx.x;
    for (int i = tid; i < HH*CIN*3; i += 256) { sw[0][i]=w1[i]; sw[1][i]=w2[i]; sw[2][i]=w3[i]; }
    if (tid < HH) { sb[0][tid]=b1[tid]; sb[1][tid]=b2[tid]; sb[2][tid]=b3[tid]; }
    __syncthreads();

    int h  = tid & 63;
    int py = tid >> 6;
    int pos = blockIdx.x*4 + py;                 // pos = (n*B + b)*T + t
    int t  = pos % TTI;
    int nb = pos / TTI;
    int b  = nb % BB;
    int n  = nb / BB;

    float xv[3][CIN];
#pragma unroll
    for (int k = 0; k < 3; k++) {
        int t2 = t + k - 1;
        if (t2 >= 0 && t2 < TTI) {
#pragma unroll
            for (int c = 0; c < CIN; c++)
                xv[k][c] = X[((b*TTI + t2)*NN + n)*CIN + c];
        } else {
            xv[k][0] = 0.f; xv[k][1] = 0.f;
        }
    }
    float p = sb[0][h], q = sb[1][h], r = sb[2][h];
#pragma unroll
    for (int c = 0; c < CIN; c++)
#pragma unroll
        for (int k = 0; k < 3; k++) {
            float v = xv[k][c];
            p += v * sw[0][h*6 + c*3 + k];
            q += v * sw[1][h*6 + c*3 + k];
            r += v * sw[2][h*6 + c*3 + k];
        }
    float sg = 1.f / (1.f + expf(-q));
    g_T0[pos*HH + h] = fmaxf(p*sg + r, 0.f);
}

// single-block exclusive scan of g_cnt -> g_rowptr, g_cursor; also g_dis
__global__ void scan_kernel() {
    __shared__ int s[1024];
    int tid = threadIdx.x;
    int lo = tid * 10;
    int sum = 0;
    for (int r = lo; r < lo+10 && r < NN; r++) {
        sum += g_cnt[r];
        float d = g_degw[r];
        g_dis[r] = d > 0.f ? rsqrtf(d) : 0.f;
    }
    s[tid] = sum;
    __syncthreads();
    for (int off = 1; off < 1024; off <<= 1) {
        int v = (tid >= off) ? s[tid-off] : 0;
        __syncthreads();
        s[tid] += v;
        __syncthreads();
    }
    int run = s[tid] - sum;   // exclusive prefix
    for (int r = lo; r < lo+10 && r < NN; r++) {
        g_rowptr[r] = run;
        g_cursor[r] = run;
        run += g_cnt[r];
    }
    if (tid == 1023) g_rowptr[NN] = s[1023];
}

__global__ void scatter_kernel(const int* __restrict__ row, const int* __restrict__ col,
                               const float* __restrict__ ew) {
    int e = blockIdx.x*256 + threadIdx.x;
    if (e < NE) {
        int r = row[e], c = col[e];
        int p = atomicAdd(&g_cursor[r], 1);
        g_colidx[p] = c;
        g_ew[p] = -g_dis[r] * ew[e] * g_dis[c];   // L_hat weight (sym norm, lambda_max=2)
    }
}

// ---------------- graph prop: y[n,:] = sum_e w[e] * x[col[e],:] ----------------
// grid (NN, 6): blockIdx.x fastest -> all nodes of one 1024-float feature chunk
// run together => 41MB L2-resident working set per chunk.
__global__ __launch_bounds__(256) void prop_kernel(int mode) {
    const float4* __restrict__ x = (const float4*)(mode ? g_Y1 : g_T0);
    float4* __restrict__ y       = (float4*)(mode ? g_Y2 : g_Y1);
    int n = blockIdx.x;
    int f = blockIdx.y*256 + threadIdx.x;     // float4 index in [0,1536)
    int beg = g_rowptr[n], end = g_rowptr[n+1];
    float4 acc = make_float4(0.f, 0.f, 0.f, 0.f);
    int e = beg;
    for (; e + 4 <= end; e += 4) {
        int   c0 = g_colidx[e],   c1 = g_colidx[e+1], c2 = g_colidx[e+2], c3 = g_colidx[e+3];
        float w0 = g_ew[e],       w1 = g_ew[e+1],     w2 = g_ew[e+2],     w3 = g_ew[e+3];
        float4 v0 = x[c0*F4 + f], v1 = x[c1*F4 + f],  v2 = x[c2*F4 + f],  v3 = x[c3*F4 + f];
        acc.x += w0*v0.x + w1*v1.x + w2*v2.x + w3*v3.x;
        acc.y += w0*v0.y + w1*v1.y + w2*v2.y + w3*v3.y;
        acc.z += w0*v0.z + w1*v1.z + w2*v2.z + w3*v3.z;
        acc.w += w0*v0.w + w1*v1.w + w2*v2.w + w3*v3.w;
    }
    for (; e < end; e++) {
        int c = g_colidx[e]; float w = g_ew[e];
        float4 v = x[c*F4 + f];
        acc.x += w*v.x; acc.y += w*v.y; acc.z += w*v.z; acc.w += w*v.w;
    }
    y[n*F4 + f] = acc;
}

// ---------------- cheb combine: S = relu(T0@W0 + Y1@W1 + (2*Y2-T0)@W2 + b) ----
// block = 128 positions. Position-packed f32x2: thread = (og=lane, pg=warp),
// 16 positions per thread as 8 packed pairs. x transposed [m][i][p] stride 136.
#define CMB_WS_F  (3*64*64)          /* 12288 */
#define CMB_XS_ST 136
#define CMB_XS_F  (3*64*CMB_XS_ST)   /* 26112 */
#define CMB_SMEM_BYTES ((CMB_WS_F + CMB_XS_F + 64)*4)
__global__ __launch_bounds__(256) void combine_kernel(const float* __restrict__ Wc,
                                                      const float* __restrict__ bias) {
    extern __shared__ float sm[];
    float* Ws = sm;                         // [m*4096 + i*64 + h]
    float* xs = sm + CMB_WS_F;              // [m*8704 + i*136 + p]
    float* bs = xs + CMB_XS_F;
    int tid = threadIdx.x;
    for (int idx = tid; idx < 3*64*64; idx += 256) Ws[idx] = Wc[idx];
    if (tid < 64) bs[tid] = bias[tid];
    int base = blockIdx.x * 128 * 64;       // 128 positions * 64 features
    {
        int wid = tid >> 5, lane = tid & 31;
        int i0 = 2*lane;
        for (int r = wid; r < 128; r += 8) {
            int go = base + r*64 + i0;
            float2 a = *(const float2*)&g_T0[go];
            float2 u = *(const float2*)&g_Y1[go];
            float2 v = *(const float2*)&g_Y2[go];
            xs[i0*CMB_XS_ST + r]             = a.x;
            xs[(i0+1)*CMB_XS_ST + r]         = a.y;
            xs[8704 + i0*CMB_XS_ST + r]      = u.x;
            xs[8704 + (i0+1)*CMB_XS_ST + r]  = u.y;
            xs[17408 + i0*CMB_XS_ST + r]     = 2.f*v.x - a.x;
            xs[17408 + (i0+1)*CMB_XS_ST + r] = 2.f*v.y - a.y;
        }
    }
    __syncthreads();

    int og = tid & 31, pg = tid >> 5;
    int p0 = pg * 16;                       // 16 positions per thread (8 pairs)
    ull acc[2][8];
    {
        ull b0 = pack2(bs[og], bs[og]);
        ull b1_ = pack2(bs[og+32], bs[og+32]);
#pragma unroll
        for (int j = 0; j < 8; j++) { acc[0][j] = b0; acc[1][j] = b1_; }
    }
    for (int i = 0; i < 64; i++) {
        float w0a = Ws[i*64+og],        w0b = Ws[i*64+og+32];
        float w1a = Ws[4096+i*64+og],   w1b = Ws[4096+i*64+og+32];
        float w2a = Ws[8192+i*64+og],   w2b = Ws[8192+i*64+og+32];
        ull W0a = pack2(w0a,w0a), W0b = pack2(w0b,w0b);
        ull W1a = pack2(w1a,w1a), W1b = pack2(w1b,w1b);
        ull W2a = pack2(w2a,w2a), W2b = pack2(w2b,w2b);
        const float* x0 = xs + i*CMB_XS_ST + p0;
        const float* x1 = x0 + 8704;
        const float* x2 = x0 + 17408;
#pragma unroll
        for (int q = 0; q < 4; q++) {
            ulonglong2 v0 = *(const ulonglong2*)(x0 + 4*q);
            ulonglong2 v1 = *(const ulonglong2*)(x1 + 4*q);
            ulonglong2 v2 = *(const ulonglong2*)(x2 + 4*q);
            fma2(acc[0][2*q],   v0.x, W0a); fma2(acc[1][2*q],   v0.x, W0b);
            fma2(acc[0][2*q+1], v0.y, W0a); fma2(acc[1][2*q+1], v0.y, W0b);
            fma2(acc[0][2*q],   v1.x, W1a); fma2(acc[1][2*q],   v1.x, W1b);
            fma2(acc[0][2*q+1], v1.y, W1a); fma2(acc[1][2*q+1], v1.y, W1b);
            fma2(acc[0][2*q],   v2.x, W2a); fma2(acc[1][2*q],   v2.x, W2b);
            fma2(acc[0][2*q+1], v2.y, W2a); fma2(acc[1][2*q+1], v2.y, W2b);
        }
    }
#pragma unroll
    for (int j = 0; j < 8; j++) {
        float v0, v1;
        unpack2(v0, v1, acc[0][j]);
        g_S[base + (p0+2*j)*64 + og]        = fmaxf(v0, 0.f);
        g_S[base + (p0+2*j+1)*64 + og]      = fmaxf(v1, 0.f);
        unpack2(v0, v1, acc[1][j]);
        g_S[base + (p0+2*j)*64 + og + 32]   = fmaxf(v0, 0.f);
        g_S[base + (p0+2*j+1)*64 + og + 32] = fmaxf(v1, 0.f);
    }
}

// ---------------- temporal conv 2: g_S[N,B,T,H] -> out[B,T,N,H] ---------------
// block = 16 (n,b) pairs (192 positions). Position-packed f32x2; x transposed
// [c][pair*14+tt] (stride 226, halo zeros). Tap operands: A=(t,t+1), B=(t+2,t+3)
// aligned LDS.64; odd tap M=(hiA, loB) via register funnel.
#define T2_W_F    (3*192*65)         /* 37440 */
#define T2_XT_ST  226
#define T2_XT_F   (64*T2_XT_ST)      /* 14464 */
#define T2_SMEM_BYTES ((T2_W_F + T2_XT_F + 192)*4)
__global__ __launch_bounds__(256) void tconv2_kernel(
        const float* __restrict__ w1, const float* __restrict__ b1,
        const float* __restrict__ w2, const float* __restrict__ b2,
        const float* __restrict__ w3, const float* __restrict__ b3,
        float* __restrict__ out) {
    extern __shared__ float sm[];
    float* Wl = sm;                         // [m*12480 + j*65 + o], j = c*3+k
    float* xt = Wl + T2_W_F;                // [c*226 + pair*14 + tt]
    float* bs = xt + T2_XT_F;               // [m*64 + o]
    int tid = threadIdx.x;
    for (int idx = tid; idx < 64*192; idx += 256) {
        int o = idx / 192, j = idx - o*192;
        Wl[j*65 + o]         = w1[idx];
        Wl[12480 + j*65 + o] = w2[idx];
        Wl[24960 + j*65 + o] = w3[idx];
    }
    if (tid < 64) { bs[tid]=b1[tid]; bs[64+tid]=b2[tid]; bs[128+tid]=b3[tid]; }
    int nb0 = blockIdx.x * 16;
    {
        int wid = tid >> 5, lane = tid & 31;
        int c0 = 2*lane;
        for (int r = wid; r < 192; r += 8) {
            int pair = r / 12, t = r - pair*12;
            float2 v = *(const float2*)&g_S[(nb0+pair)*768 + t*64 + c0];
            xt[c0*T2_XT_ST + pair*14 + t + 1]     = v.x;
            xt[(c0+1)*T2_XT_ST + pair*14 + t + 1] = v.y;
        }
        for (int idx = tid; idx < 64*32; idx += 256) {
            int c = idx >> 5, r = idx & 31;
            int pair = r >> 1, e = r & 1;
            xt[c*T2_XT_ST + pair*14 + (e ? 13 : 0)] = 0.f;
        }
    }
    __syncthreads();

    int og = tid & 31, pg = tid >> 5;
    for (int ch = 0; ch < 3; ch++) {
        int pbase = ch*64 + pg*8;           // even
        int xb[4], pr_pair[4], pr_t[4];
        ull acc[3][2][4];
#pragma unroll
        for (int pr = 0; pr < 4; pr++) {
            int pos = pbase + 2*pr;
            int pair = pos / 12, t = pos - pair*12;   // t even
            pr_pair[pr] = pair; pr_t[pr] = t;
            xb[pr] = pair*14 + t;
        }
#pragma unroll
        for (int m = 0; m < 3; m++) {
            ull b0 = pack2(bs[m*64+og], bs[m*64+og]);
            ull b1_ = pack2(bs[m*64+og+32], bs[m*64+og+32]);
#pragma unroll
            for (int pr = 0; pr < 4; pr++) { acc[m][0][pr] = b0; acc[m][1][pr] = b1_; }
        }
        for (int c = 0; c < 64; c++) {
            const float* xr = xt + c*T2_XT_ST;
            ull A[4], Bv[4], M[4];
#pragma unroll
            for (int pr = 0; pr < 4; pr++) {
                A[pr]  = *(const ull*)(xr + xb[pr]);
                Bv[pr] = *(const ull*)(xr + xb[pr] + 2);
                float alo, ahi, blo, bhi;
                unpack2(alo, ahi, A[pr]);
                unpack2(blo, bhi, Bv[pr]);
                M[pr] = pack2(ahi, blo);
            }
            int j65 = (c*3)*65;
#pragma unroll
            for (int m = 0; m < 3; m++) {
                const float* wb = Wl + m*12480 + j65;
                float w00 = wb[og],      w01 = wb[og+32];
                float w10 = wb[65+og],   w11 = wb[65+og+32];
                float w20 = wb[130+og],  w21 = wb[130+og+32];
                ull W00 = pack2(w00,w00), W01 = pack2(w01,w01);
                ull W10 = pack2(w10,w10), W11 = pack2(w11,w11);
                ull W20 = pack2(w20,w20), W21 = pack2(w21,w21);
#pragma unroll
                for (int pr = 0; pr < 4; pr++) {
                    fma2(acc[m][0][pr], A[pr],  W00);
                    fma2(acc[m][0][pr], M[pr],  W10);
                    fma2(acc[m][0][pr], Bv[pr], W20);
                    fma2(acc[m][1][pr], A[pr],  W01);
                    fma2(acc[m][1][pr], M[pr],  W11);
                    fma2(acc[m][1][pr], Bv[pr], W21);
                }
            }
        }
#pragma unroll
        for (int pr = 0; pr < 4; pr++) {
            int nb = nb0 + pr_pair[pr]; int n = nb >> 3; int b = nb & 7;
            int t = pr_t[pr];
            int obase = ((b*TTI + t)*NN + n)*64;
            int obase2 = obase + NN*64;     // t+1
            float Pl,Ph,Ql,Qh,Rl,Rh;
            // half 0 (og)
            unpack2(Pl, Ph, acc[0][0][pr]);
            unpack2(Ql, Qh, acc[1][0][pr]);
            unpack2(Rl, Rh, acc[2][0][pr]);
            out[obase  + og] = fmaxf(Pl/(1.f+expf(-Ql)) + Rl, 0.f);
            out[obase2 + og] = fmaxf(Ph/(1.f+expf(-Qh)) + Rh, 0.f);
            // half 1 (og+32)
            unpack2(Pl, Ph, acc[0][1][pr]);
            unpack2(Ql, Qh, acc[1][1][pr]);
            unpack2(Rl, Rh, acc[2][1][pr]);
            out[obase  + og + 32] = fmaxf(Pl/(1.f+expf(-Ql)) + Rl, 0.f);
            out[obase2 + og + 32] = fmaxf(Ph/(1.f+expf(-Qh)) + Rh, 0.f);
        }
    }
}

// zero the accumulated histograms for the NEXT call (globals are zero at load)
__global__ void cleanup_kernel() {
    int i = blockIdx.x*256 + threadIdx.x;
    if (i < NN) { g_degw[i] = 0.f; g_cnt[i] = 0; }
}

// ---------------- launch ----------------
extern "C" void kernel_launch(void* const* d_in, const int* in_sizes, int n_in,
                              void* d_out, int out_size) {
    const float* X    = (const float*)d_in[0];
    const int*   ei   = (const int*)  d_in[1];
    const float* ew   = (const float*)d_in[2];
    const float* t1w1 = (const float*)d_in[3];  const float* t1b1 = (const float*)d_in[4];
    const float* t1w2 = (const float*)d_in[5];  const float* t1b2 = (const float*)d_in[6];
    const float* t1w3 = (const float*)d_in[7];  const float* t1b3 = (const float*)d_in[8];
    const float* cW   = (const float*)d_in[9];  const float* cb   = (const float*)d_in[10];
    const float* t2w1 = (const float*)d_in[11]; const float* t2b1 = (const float*)d_in[12];
    const float* t2w2 = (const float*)d_in[13]; const float* t2b2 = (const float*)d_in[14];
    const float* t2w3 = (const float*)d_in[15]; const float* t2b3 = (const float*)d_in[16];
    float* out = (float*)d_out;
    const int* row = ei;
    const int* col = ei + NE;

    cudaFuncSetAttribute(combine_kernel, cudaFuncAttributeMaxDynamicSharedMemorySize,
                         CMB_SMEM_BYTES);
    cudaFuncSetAttribute(tconv2_kernel, cudaFuncAttributeMaxDynamicSharedMemorySize,
                         T2_SMEM_BYTES);

    prep_kernel   <<<T1_BLOCKS + HIST_BLOCKS, 256>>>(X, t1w1,t1b1, t1w2,t1b2, t1w3,t1b3,
                                                     row, ew);
    scan_kernel   <<<1, 1024>>>();
    scatter_kernel<<<(NE+255)/256, 256>>>(row, col, ew);

    prop_kernel   <<<dim3(NN, 6), 256>>>(0);   // Y1 = L * T0   (profiled launch idx 3)
    prop_kernel   <<<dim3(NN, 6), 256>>>(1);   // Y2 = L * Y1

    combine_kernel<<<NBT/128, 256, CMB_SMEM_BYTES>>>(cW, cb);

    tconv2_kernel <<<NN*BB/16, 256, T2_SMEM_BYTES>>>(
        t2w1,t2b1, t2w2,t2b2, t2w3,t2b3, out);

    cleanup_kernel<<<(NN+255)/256, 256>>>();
}